// round 1
// baseline (speedup 1.0000x reference)
#include <cuda_runtime.h>
#include <cuda_bf16.h>

// Problem constants (fixed by reference setup_inputs)
#define B_  8
#define C_  3
#define H_  1024
#define W_  1024
#define HO_ 256
#define WO_ 256
#define KS_ 3
#define KK_ (KS_*KS_)    // 9
#define SCALE_ 4
#define HP_ (H_ + 2)     // padded 1026
#define WP_ (W_ + 2)

// reflect-map a padded index (0..HP_-1) to original index (0..H_-1), pad=1,
// numpy 'reflect' (mirror without edge repeat): imgp[0]=img[1], imgp[H+1]=img[H-2]
__device__ __forceinline__ int reflect_map(int i, int n) {
    int j = i - 1;
    j = (j < 0) ? -j : j;
    j = (j >= n) ? (2 * n - 2 - j) : j;
    return j;
}

__global__ __launch_bounds__(256, 4)
void adaptive_downsample_kernel(
    const float* __restrict__ img,        // (B,C,H,W)
    const float* __restrict__ kernels,    // (B,9,HO,WO)
    const float* __restrict__ offs_h,     // (B,9,HO,WO)
    const float* __restrict__ offs_v,     // (B,9,HO,WO)
    const float* __restrict__ offset_unit,// (1,)
    float* __restrict__ out)              // (B,C,HO,WO)
{
    const int ow = blockIdx.x * blockDim.x + threadIdx.x;  // 0..255
    const int oh = blockIdx.y * blockDim.y + threadIdx.y;  // 0..255
    const int b  = blockIdx.z;
    if (ow >= WO_ || oh >= HO_) return;

    const float ou = __ldg(offset_unit);

    const float cy = ((float)oh + 0.5f) * (float)SCALE_ - 0.5f;
    const float cx = ((float)ow + 0.5f) * (float)SCALE_ - 0.5f;

    const int pix   = oh * WO_ + ow;              // within (HO,WO) plane
    const int plane = HO_ * WO_;                  // 65536
    const long long auxb = (long long)b * KK_ * plane + pix;

    const float* imgb = img + (long long)b * C_ * H_ * W_;

    float acc0 = 0.f, acc1 = 0.f, acc2 = 0.f;

    #pragma unroll
    for (int k = 0; k < KK_; ++k) {
        const float kw  = __ldg(kernels + auxb + (long long)k * plane);
        const float ovv = __ldg(offs_v  + auxb + (long long)k * plane);
        const float ohh = __ldg(offs_h  + auxb + (long long)k * plane);

        const float ky = (float)(k / KS_);
        const float kx = (float)(k % KS_);

        const float py = cy + ky + ovv * ou;
        const float px = cx + kx + ohh * ou;

        const float y0f = floorf(py);
        const float x0f = floorf(px);
        const float beta  = py - y0f;
        const float alpha = px - x0f;

        int y0 = (int)y0f;  y0 = min(max(y0, 0), HP_ - 1);
        int y1 = min(y0 + 1, HP_ - 1);
        int x0 = (int)x0f;  x0 = min(max(x0, 0), WP_ - 1);
        int x1 = min(x0 + 1, WP_ - 1);

        // map padded coords -> original image coords (reflect pad=1)
        const int ry0 = reflect_map(y0, H_);
        const int ry1 = reflect_map(y1, H_);
        const int rx0 = reflect_map(x0, W_);
        const int rx1 = reflect_map(x1, W_);

        const float w00 = (1.f - alpha) * (1.f - beta) * kw;
        const float w01 = alpha * (1.f - beta) * kw;
        const float w10 = (1.f - alpha) * beta * kw;
        const float w11 = alpha * beta * kw;

        const int i00 = ry0 * W_ + rx0;
        const int i01 = ry0 * W_ + rx1;
        const int i10 = ry1 * W_ + rx0;
        const int i11 = ry1 * W_ + rx1;

        // channel 0
        {
            const float* p = imgb;
            acc0 += w00 * __ldg(p + i00) + w01 * __ldg(p + i01)
                  + w10 * __ldg(p + i10) + w11 * __ldg(p + i11);
        }
        // channel 1
        {
            const float* p = imgb + H_ * W_;
            acc1 += w00 * __ldg(p + i00) + w01 * __ldg(p + i01)
                  + w10 * __ldg(p + i10) + w11 * __ldg(p + i11);
        }
        // channel 2
        {
            const float* p = imgb + 2 * H_ * W_;
            acc2 += w00 * __ldg(p + i00) + w01 * __ldg(p + i01)
                  + w10 * __ldg(p + i10) + w11 * __ldg(p + i11);
        }
    }

    const long long ob = (long long)b * C_ * plane + pix;
    out[ob]             = acc0;
    out[ob + plane]     = acc1;
    out[ob + 2 * plane] = acc2;
}

extern "C" void kernel_launch(void* const* d_in, const int* in_sizes, int n_in,
                              void* d_out, int out_size) {
    const float* img     = (const float*)d_in[0];
    const float* kernels = (const float*)d_in[1];
    const float* offs_h  = (const float*)d_in[2];
    const float* offs_v  = (const float*)d_in[3];
    const float* ou      = (const float*)d_in[4];
    float* out = (float*)d_out;

    dim3 block(32, 8, 1);
    dim3 grid(WO_ / 32, HO_ / 8, B_);
    adaptive_downsample_kernel<<<grid, block>>>(img, kernels, offs_h, offs_v, ou, out);
}